// round 15
// baseline (speedup 1.0000x reference)
#include <cuda_runtime.h>
#include <cuda_fp16.h>
#include <math.h>
#include <stdint.h>

// ---------------------------------------------------------------------------
// Problem constants
// ---------------------------------------------------------------------------
#define BB   4
#define LL   2048
#define DIMC 1024
#define DFFC 4096
#define MROWS (BB*LL)        // 8192
#define NCHUNK 64
#define CHUNK  (LL/NCHUNK)   // 32
#define EPSLN 1e-5f

// GEMM tiling (fp16 mma.sync m16n8k16, fp32 accumulate)
#define BM 128
#define BNT 128
#define BKT 32
#define ASTRH 40
#define STAGES 3
#define STAGE_BYTES ((BM + BNT) * ASTRH * 2)     // 20480
#define GSMEM (STAGES * STAGE_BYTES)             // 61440
#define A_SMEM_BYTES (BM * ASTRH * 2)

#define G1_MT (MROWS/BM)     // 64
#define G1_NT (DFFC/BNT)     // 32
#define G1_TILES (G1_MT*G1_NT)   // 2048
#define G2_NT (DIMC/BNT)     // 8
#define G2_TILES (G1_MT*G2_NT)   // 512

#define CV1_BLKS ((DFFC/32)*(DIMC/32))   // 4096
#define CV2_BLKS ((DIMC/32)*(DFFC/32))   // 4096

// mega-kernel block layout: [pass3 1024][ln2 8192][G1 2048][G2 512]
#define MB_P3   (BB*NCHUNK*4)            // 1024
#define MO_LN2  MB_P3                    // 1024
#define MO_G1   (MO_LN2 + MROWS)         // 9216
#define MO_G2   (MO_G1 + G1_TILES)       // 11264
#define MB_TOT  (MO_G2 + G2_TILES)       // 11776

// sync counters: cntD[256] (pass3->ln2), cntE[64] (ln2->G1), cntF[64] (G1->G2)
#define SY_D 0
#define SY_E 256
#define SY_F 320
#define SY_N 384

// ---------------------------------------------------------------------------
// Scratch (device globals: allocation-free rule)
// ---------------------------------------------------------------------------
__device__ float  g_y1[(size_t)MROWS*DIMC];
__device__ __half g_h16[(size_t)MROWS*DIMC];
__device__ __half g_act16[(size_t)MROWS*DFFC];
__device__ __half g_w1t[(size_t)DFFC*DIMC];
__device__ __half g_w2t[(size_t)DIMC*DFFC];
__device__ float2 g_stat[MROWS];
__device__ float2 g_chunkS[BB*NCHUNK*DIMC];
__device__ float2 g_initS[BB*NCHUNK*DIMC];
__device__ int    g_sync[SY_N];

// ---------------------------------------------------------------------------
// PTX helpers
// ---------------------------------------------------------------------------
__device__ __forceinline__ void cp16(uint32_t s, const void* gp) {
    asm volatile("cp.async.cg.shared.global [%0], [%1], 16;"
                 :: "r"(s), "l"(gp) : "memory");
}
__device__ __forceinline__ void cp_commit() {
    asm volatile("cp.async.commit_group;" ::: "memory");
}
template<int N> __device__ __forceinline__ void cp_wait() {
    asm volatile("cp.async.wait_group %0;" :: "n"(N) : "memory");
}
__device__ __forceinline__ void ldsm_x4(uint32_t& r0, uint32_t& r1,
                                        uint32_t& r2, uint32_t& r3, uint32_t a) {
    asm volatile("ldmatrix.sync.aligned.m8n8.x4.shared.b16 {%0,%1,%2,%3}, [%4];"
                 : "=r"(r0), "=r"(r1), "=r"(r2), "=r"(r3) : "r"(a));
}
__device__ __forceinline__ void mma_f16(float* d, const uint32_t* a, const uint32_t* b) {
    asm volatile("mma.sync.aligned.m16n8k16.row.col.f32.f16.f16.f32 "
                 "{%0,%1,%2,%3}, {%4,%5,%6,%7}, {%8,%9}, {%0,%1,%2,%3};"
                 : "+f"(d[0]), "+f"(d[1]), "+f"(d[2]), "+f"(d[3])
                 : "r"(a[0]), "r"(a[1]), "r"(a[2]), "r"(a[3]),
                   "r"(b[0]), "r"(b[1]));
}
__device__ __forceinline__ int ld_acquire(const int* p) {
    int v;
    asm volatile("ld.global.acquire.gpu.b32 %0, [%1];" : "=r"(v) : "l"(p) : "memory");
    return v;
}
__device__ __forceinline__ void block_wait(const int* p, int target) {
    if (threadIdx.x == 0) {
        while (ld_acquire(p) < target) __nanosleep(64);
    }
    __syncthreads();
    __threadfence();
}
__device__ __forceinline__ void block_signal(int* p) {
    __threadfence();
    __syncthreads();
    if (threadIdx.x == 0) atomicAdd(p, 1);
}

// ---------------------------------------------------------------------------
// Row reduction helper (256 threads, D=1024 as float4)
// ---------------------------------------------------------------------------
__device__ __forceinline__ void row_stats(float4 v, float& mu, float& rs) {
    float s  = v.x + v.y + v.z + v.w;
    float sq = v.x*v.x + v.y*v.y + v.z*v.z + v.w*v.w;
    #pragma unroll
    for (int o = 16; o > 0; o >>= 1) {
        s  += __shfl_xor_sync(0xffffffffu, s,  o);
        sq += __shfl_xor_sync(0xffffffffu, sq, o);
    }
    __shared__ float ss[8], ssq[8];
    int w = threadIdx.x >> 5, lane = threadIdx.x & 31;
    if (lane == 0) { ss[w] = s; ssq[w] = sq; }
    __syncthreads();
    s = 0.f; sq = 0.f;
    #pragma unroll
    for (int i = 0; i < 8; i++) { s += ss[i]; sq += ssq[i]; }
    mu = s * (1.0f / DIMC);
    float var = sq * (1.0f / DIMC) - mu * mu;
    rs = rsqrtf(var + EPSLN);
}

__device__ __forceinline__ void convT_body(
    const float* __restrict__ in, __half* __restrict__ out,
    int R, int C, int bx, int by)
{
    __shared__ float t[32][33];
    int x = threadIdx.x & 31, y = threadIdx.x >> 5;
    #pragma unroll
    for (int i = 0; i < 32; i += 8)
        t[y + i][x] = in[(size_t)(by*32 + y + i) * C + bx*32 + x];
    __syncthreads();
    #pragma unroll
    for (int i = 0; i < 32; i += 8)
        out[(size_t)(bx*32 + y + i) * R + by*32 + x] = __float2half(t[x][y + i]);
}

// ---------------------------------------------------------------------------
// Launch 1: rowstats(x) + convT(w1) + zero sync counters
// ---------------------------------------------------------------------------
__global__ __launch_bounds__(256) void prep_kernel(
    const float* __restrict__ x, float2* __restrict__ stat,
    const float* __restrict__ w1, __half* __restrict__ w1t)
{
    int bid = blockIdx.x;
    if (bid < MROWS) {
        if (bid == 0 && threadIdx.x < SY_N) g_sync[threadIdx.x] = 0;
        float4 v = ((const float4*)(x + (size_t)bid * DIMC))[threadIdx.x];
        float mu, rs; row_stats(v, mu, rs);
        if (threadIdx.x == 0) stat[bid] = make_float2(mu, rs);
    } else {
        int b2 = bid - MROWS;
        convT_body(w1, w1t, DIMC, DFFC, b2 % (DFFC/32), b2 / (DFFC/32));
    }
}

// ---------------------------------------------------------------------------
// Spiral conv pieces
// ---------------------------------------------------------------------------
__device__ __forceinline__ void load_phazor(const float* __restrict__ phz, int d,
                                            float& pr, float& pi)
{
    pr = phz[2*d]; pi = phz[2*d+1];
    float pa = sqrtf(pr*pr + pi*pi);
    float sc = expf(-pa) / pa;
    pr *= sc; pi *= sc;
}

// Launch 2: pass1 only
__global__ __launch_bounds__(256) void spiral_pass1(
    const float* __restrict__ x, const float* __restrict__ phz,
    const float* __restrict__ phz_init,
    const float* __restrict__ lng, const float* __restrict__ lnb)
{
    int bc = blockIdx.x >> 2;
    int d  = ((blockIdx.x & 3) << 8) + threadIdx.x;
    int b  = bc / NCHUNK, c = bc % NCHUNK;

    float pr, pi; load_phazor(phz, d, pr, pi);
    float ir = phz_init[2*d], ii = phz_init[2*d+1];
    float gg = lng[d], bb2 = lnb[d];

    int row0 = b*LL + c*CHUNK;
    const float*  xp  = x + (size_t)row0 * DIMC + d;
    const float2* stp = g_stat + row0;

    float sr = 0.f, si = 0.f;
    #pragma unroll 8
    for (int s = 0; s < CHUNK; s++) {
        float2 st = stp[s];
        float hv = (xp[(size_t)s*DIMC] - st.x) * st.y * gg + bb2;
        float nr = pr*sr - pi*si + ir*hv;
        float ni = pr*si + pi*sr + ii*hv;
        sr = nr; si = ni;
    }
    g_chunkS[(size_t)bc*DIMC + d] = make_float2(sr, si);
}

// Launch 3: pass2 (16 blocks) + convT(w2) (4096 blocks)
__global__ __launch_bounds__(256) void pass2_convT_kernel(
    const float* __restrict__ phz,
    const float* __restrict__ last_re, const float* __restrict__ last_im,
    const float* __restrict__ w2, __half* __restrict__ w2t)
{
    int bid = blockIdx.x;
    if (bid < 16) {
        int idx = bid * 256 + threadIdx.x;
        int b = idx / DIMC, d = idx % DIMC;

        float pr, pi; load_phazor(phz, d, pr, pi);
        float cr = pr, ci = pi;           // p̂^CHUNK via 5 squarings (CHUNK=32)
        #pragma unroll
        for (int i = 0; i < 5; i++) {
            float nr = cr*cr - ci*ci;
            ci = 2.f*cr*ci; cr = nr;
        }
        float sr = last_re[idx], si = last_im[idx];
        #pragma unroll 8
        for (int c = 0; c < NCHUNK; c++) {
            size_t off = ((size_t)b*NCHUNK + c)*DIMC + d;
            g_initS[off] = make_float2(sr, si);
            float2 S = g_chunkS[off];
            float nr = cr*sr - ci*si + S.x;
            float ni = cr*si + ci*sr + S.y;
            sr = nr; si = ni;
        }
    } else {
        int b3 = bid - 16;
        convT_body(w2, w2t, DFFC, DIMC, b3 % (DIMC/32), b3 / (DIMC/32));
    }
}

// ---------------------------------------------------------------------------
// GEMM tile body (fp16 K-major, 3-stage cp.async, ldmatrix, mma.sync)
// MODE 0: C = fp16(silu(AB+bias));  MODE 1: C = f32(AB+bias+resid)
// ---------------------------------------------------------------------------
template<int MODE, int NN, int KK>
__device__ __forceinline__ void gemm_body(
    const __half* __restrict__ A, const __half* __restrict__ Bt,
    const float* __restrict__ bias, const float* __restrict__ resid,
    void* __restrict__ Cv, int bm, int bn, char* dsm)
{
    constexpr int NT = 4;
    constexpr int NK = KK / BKT;

    uint32_t sbase = (uint32_t)__cvta_generic_to_shared(dsm);

    int tid  = threadIdx.x;
    int wid  = tid >> 5, lane = tid & 31;
    int g    = lane >> 2, c = lane & 3;
    int wm   = wid >> 2, wn = wid & 3;

    float acc[4][NT][4];
    #pragma unroll
    for (int mt = 0; mt < 4; mt++)
        #pragma unroll
        for (int nt = 0; nt < NT; nt++)
            #pragma unroll
            for (int i = 0; i < 4; i++) acc[mt][nt][i] = 0.f;

    const __half* Abase = A  + (size_t)bm * KK;
    const __half* Bbase = Bt + (size_t)bn * KK;

    int arow = tid >> 2, aq = tid & 3;

    auto load_tile = [&](int k0, int stage) {
        uint32_t sa = sbase + (uint32_t)stage * STAGE_BYTES;
        uint32_t sb = sa + A_SMEM_BYTES;
        #pragma unroll
        for (int i = 0; i < 2; i++) {
            int row = arow + i * 64;
            cp16(sa + (uint32_t)row * (ASTRH*2) + aq * 16,
                 Abase + (size_t)row * KK + k0 + aq * 8);
        }
        #pragma unroll
        for (int i = 0; i < 2; i++) {
            int row = arow + i * 64;
            cp16(sb + (uint32_t)row * (ASTRH*2) + aq * 16,
                 Bbase + (size_t)row * KK + k0 + aq * 8);
        }
        cp_commit();
    };

    uint32_t lmo = (uint32_t)(lane & 15) * (ASTRH*2) + (uint32_t)(lane >> 4) * 16;
    uint32_t a_lm = lmo + (uint32_t)(wm * 64) * (ASTRH*2);
    uint32_t b_lm = lmo + (uint32_t)A_SMEM_BYTES + (uint32_t)(wn * 32) * (ASTRH*2);

    #pragma unroll
    for (int p = 0; p < STAGES - 1; p++) load_tile(p * BKT, p);

    for (int k = 0; k < NK; k++) {
        cp_wait<STAGES - 2>();
        __syncthreads();

        int nk = k + STAGES - 1;
        if (nk < NK) load_tile(nk * BKT, nk % STAGES);
        else         cp_commit();

        uint32_t stg = sbase + (uint32_t)(k % STAGES) * STAGE_BYTES;

        #pragma unroll
        for (int ks = 0; ks < 2; ks++) {
            uint32_t af[4][4], bf[NT][2];
            #pragma unroll
            for (int mt = 0; mt < 4; mt++)
                ldsm_x4(af[mt][0], af[mt][1], af[mt][2], af[mt][3],
                        stg + a_lm + (uint32_t)mt * (16*ASTRH*2) + (uint32_t)ks * 32);
            #pragma unroll
            for (int ntp = 0; ntp < NT/2; ntp++) {
                uint32_t r0, r1, r2, r3;
                ldsm_x4(r0, r1, r2, r3,
                        stg + b_lm + (uint32_t)ntp * (16*ASTRH*2) + (uint32_t)ks * 32);
                bf[2*ntp][0]   = r0; bf[2*ntp+1][0] = r1;
                bf[2*ntp][1]   = r2; bf[2*ntp+1][1] = r3;
            }
            #pragma unroll
            for (int mt = 0; mt < 4; mt++)
                #pragma unroll
                for (int nt = 0; nt < NT; nt++)
                    mma_f16(acc[mt][nt], af[mt], bf[nt]);
        }
    }
    cp_wait<0>();

    #pragma unroll
    for (int mt = 0; mt < 4; mt++) {
        int r0 = bm + wm*64 + mt*16 + g;
        size_t ro0 = (size_t)r0 * NN;
        size_t ro1 = (size_t)(r0 + 8) * NN;
        #pragma unroll
        for (int nt = 0; nt < NT; nt++) {
            int col = bn + wn*32 + nt*8 + 2*c;
            float2 bs = *(const float2*)(bias + col);
            float v0 = acc[mt][nt][0] + bs.x, v1 = acc[mt][nt][1] + bs.y;
            float v2 = acc[mt][nt][2] + bs.x, v3 = acc[mt][nt][3] + bs.y;
            if (MODE == 0) {
                v0 = v0 / (1.f + __expf(-v0));
                v1 = v1 / (1.f + __expf(-v1));
                v2 = v2 / (1.f + __expf(-v2));
                v3 = v3 / (1.f + __expf(-v3));
                __half* C16 = (__half*)Cv;
                *(__half2*)(C16 + ro0 + col) = __floats2half2_rn(v0, v1);
                *(__half2*)(C16 + ro1 + col) = __floats2half2_rn(v2, v3);
            } else {
                float* C = (float*)Cv;
                float2 r0v = *(const float2*)(resid + ro0 + col);
                float2 r1v = *(const float2*)(resid + ro1 + col);
                *(float2*)(C + ro0 + col) = make_float2(v0 + r0v.x, v1 + r0v.y);
                *(float2*)(C + ro1 + col) = make_float2(v2 + r1v.x, v3 + r1v.y);
            }
        }
    }
}

// ---------------------------------------------------------------------------
// Launch 4 (mega): [pass3][ln2][GEMM1][GEMM2] with arrive-counter chaining.
// All waits reference strictly lower-bid producers -> dispatch-order safe.
// ---------------------------------------------------------------------------
__global__ __launch_bounds__(256, 2) void mega_kernel(
    const float* __restrict__ x, const float* __restrict__ phz,
    const float* __restrict__ phz_init,
    const float* __restrict__ lng, const float* __restrict__ lnb,
    const __half* __restrict__ w1t, const float* __restrict__ b1,
    const __half* __restrict__ w2t, const float* __restrict__ b2,
    float* __restrict__ out)
{
    extern __shared__ char dsm[];
    int bid = blockIdx.x;

    if (bid < MB_P3) {
        // ---- spiral pass3: y1 = Re(state) + x ----
        int bc = bid >> 2;
        int d  = ((bid & 3) << 8) + threadIdx.x;
        int b  = bc / NCHUNK, c = bc % NCHUNK;

        float pr, pi; load_phazor(phz, d, pr, pi);
        float ir = phz_init[2*d], ii = phz_init[2*d+1];
        float gg = lng[d], bb2 = lnb[d];

        int row0 = b*LL + c*CHUNK;
        const float*  xp  = x + (size_t)row0 * DIMC + d;
        const float2* stp = g_stat + row0;
        float*        yp  = g_y1 + (size_t)row0 * DIMC + d;

        float2 st0 = g_initS[(size_t)bc*DIMC + d];
        float sr = st0.x, si = st0.y;
        #pragma unroll 4
        for (int s = 0; s < CHUNK; s++) {
            float2 st = stp[s];
            float xv = xp[(size_t)s*DIMC];
            float hv = (xv - st.x) * st.y * gg + bb2;
            float nr = pr*sr - pi*si + ir*hv;
            float ni = pr*si + pi*sr + ii*hv;
            sr = nr; si = ni;
            yp[(size_t)s*DIMC] = sr + xv;
        }
        block_signal(&g_sync[SY_D + bc]);            // 4 arrivals per 32-row group
    } else if (bid < MO_G1) {
        // ---- ln2: h16 = fp16(LN(y1)) for one row ----
        int row = bid - MO_LN2;
        block_wait(&g_sync[SY_D + (row >> 5)], 4);

        size_t base = (size_t)row * DIMC;
        float4 v = ((const float4*)(g_y1 + base))[threadIdx.x];
        float mu, rs; row_stats(v, mu, rs);

        float4 gg = ((const float4*)lng)[threadIdx.x];
        float4 bb = ((const float4*)lnb)[threadIdx.x];
        float ox = (v.x - mu) * rs * gg.x + bb.x;
        float oy = (v.y - mu) * rs * gg.y + bb.y;
        float oz = (v.z - mu) * rs * gg.z + bb.z;
        float ow = (v.w - mu) * rs * gg.w + bb.w;
        __half2* oh = (__half2*)(g_h16 + base);
        oh[threadIdx.x * 2 + 0] = __floats2half2_rn(ox, oy);
        oh[threadIdx.x * 2 + 1] = __floats2half2_rn(oz, ow);

        block_signal(&g_sync[SY_E + (row >> 7)]);    // 128 arrivals per m-tile
    } else if (bid < MO_G2) {
        // ---- GEMM1 tile: act16 = fp16(silu(h16 @ w1 + b1)) ----
        int idx = bid - MO_G1;
        int m = idx >> 5, n = idx & 31;              // n fastest within m
        block_wait(&g_sync[SY_E + m], 128);
        gemm_body<0, DFFC, DIMC>(g_h16, w1t, b1, nullptr, g_act16,
                                 m * BM, n * BNT, dsm);
        block_signal(&g_sync[SY_F + m]);             // 32 arrivals per m-tile
    } else {
        // ---- GEMM2 tile: out = act16 @ w2 + b2 + y1 ----
        int idx = bid - MO_G2;
        int m = idx >> 3, n = idx & 7;
        block_wait(&g_sync[SY_F + m], G1_NT);
        gemm_body<1, DIMC, DFFC>(g_act16, w2t, b2, g_y1, out,
                                 m * BM, n * BNT, dsm);
    }
}

// ---------------------------------------------------------------------------
// Launch
// ---------------------------------------------------------------------------
extern "C" void kernel_launch(void* const* d_in, const int* in_sizes, int n_in,
                              void* d_out, int out_size)
{
    (void)in_sizes; (void)n_in; (void)out_size;
    const float* x        = (const float*)d_in[0];
    const float* ln_g     = (const float*)d_in[1];
    const float* ln_b     = (const float*)d_in[2];
    const float* phz      = (const float*)d_in[3];
    const float* phz_init = (const float*)d_in[4];
    const float* w1       = (const float*)d_in[5];
    const float* b1       = (const float*)d_in[6];
    const float* w2       = (const float*)d_in[7];
    const float* b2       = (const float*)d_in[8];
    const float* last_re  = (const float*)d_in[9];
    const float* last_im  = (const float*)d_in[10];
    float* out = (float*)d_out;

    float2 *stat_p;
    __half *w1t_p, *w2t_p;
    cudaGetSymbolAddress((void**)&stat_p, g_stat);
    cudaGetSymbolAddress((void**)&w1t_p,  g_w1t);
    cudaGetSymbolAddress((void**)&w2t_p,  g_w2t);

    cudaFuncSetAttribute((const void*)mega_kernel,
                         cudaFuncAttributeMaxDynamicSharedMemorySize, GSMEM);

    // 1) rowstats + w1 convert + zero counters
    prep_kernel<<<MROWS + CV1_BLKS, 256>>>(x, stat_p, w1, w1t_p);

    // 2) spiral pass1 (chunk partial states)
    spiral_pass1<<<BB*NCHUNK*(DIMC/256), 256>>>(x, phz, phz_init, ln_g, ln_b);

    // 3) pass2 (chunk combine) + w2 convert
    pass2_convT_kernel<<<16 + CV2_BLKS, 256>>>(phz, last_re, last_im, w2, w2t_p);

    // 4) mega: pass3 -> ln2 -> GEMM1 -> GEMM2, counter-chained in one launch
    mega_kernel<<<MB_TOT, 256, GSMEM>>>(x, phz, phz_init, ln_g, ln_b,
                                        w1t_p, b1, w2t_p, b2, out);
}